// round 13
// baseline (speedup 1.0000x reference)
#include <cuda_runtime.h>

// SMorph: out = sum_k (x_p+f_k) e^{a(x_p+f_k)} / sum_k e^{a(x_p+f_k)}
// Factored: G=exp(a*x), H=x*G, E_k=exp(a*f_k), F_k=f_k*E_k
//   num = sum_k E_k*H + F_k*G;  den = sum_k E_k*G
// R12 structure (y-register-reuse, 4x2 patch/thread, conflict-free LDS)
// + packed math with NO junk lanes:
//   acc{pA,pB} += {E,F} * {h,g}   (one fma.rn.f32x2: pA=Sum E*h, pB=Sum F*g)
//   den        += E * g           (one scalar FFMA)
//   out = (pA + pB) / den
// -> 2 fma slots per tap-output instead of 3.

namespace {
constexpr int BATCH = 8;
constexpr int HH = 192, WW = 192;
constexpr int CO = 8;
constexpr int KH = 7, KW = 7;
constexpr int HO = 186, WO = 186;

constexpr int TILE_X = 64;
constexpr int TILE_Y = 32;           // 2 rows per thread
constexpr int ITX = TILE_X + KW - 1; // 70
constexpr int ITY = TILE_Y + KH - 1; // 38
constexpr int PITCH = 71;
constexpr int OPT = 4;               // outputs per thread in x
constexpr int WINW = OPT + KW - 1;   // 10
}

__device__ __forceinline__ void vfma(unsigned long long& acc,
                                     unsigned long long a,
                                     unsigned long long b) {
    asm("fma.rn.f32x2 %0, %1, %2, %0;" : "+l"(acc) : "l"(a), "l"(b));
}

__global__ __launch_bounds__(256, 4)
void smorph_kernel(const float* __restrict__ x,
                   const float* __restrict__ filt,
                   const float* __restrict__ alpha,
                   float* __restrict__ out)
{
    __shared__ float sG[ITY * PITCH];
    __shared__ float sH[ITY * PITCH];
    __shared__ float2 sEF[KH * KW];   // {E, F}: operand of the f32x2 fma
    __shared__ float  sE[KH * KW];    // E scalar for den

    const int bc  = blockIdx.z;       // b*8 + c
    const int c   = bc & 7;
    const int tid = threadIdx.x;

    const float a = alpha[c];

    if (tid < KH * KW) {
        float f = filt[c * (KH * KW) + tid];
        float e = __expf(a * f);
        sEF[tid] = make_float2(e, f * e);
        sE[tid]  = e;
    }

    const int gx0 = blockIdx.x * TILE_X;
    const int gy0 = blockIdx.y * TILE_Y;
    const float* xb = x + (bc >> 3) * (HH * WW);

    // Cooperative tile fill: G = exp(a*x), H = x*G
    for (int i = tid; i < ITY * ITX; i += 256) {
        int iy = i / ITX;
        int ix = i - iy * ITX;
        int gy = gy0 + iy;
        int gx = gx0 + ix;
        float v = (gy < HH && gx < WW) ? xb[gy * WW + gx] : 0.0f;
        float g = __expf(a * v);
        sG[iy * PITCH + ix] = g;
        sH[iy * PITCH + ix] = v * g;
    }
    __syncthreads();

    // Warp geometry: 4 row-pairs x 8 lanes; thread owns 4 cols x 2 rows.
    const int lane = tid & 31;
    const int warp = tid >> 5;        // 0..7
    const int tx = lane & 7;          // 0..7
    const int sy = lane >> 3;         // 0..3
    const int wx = warp & 1;          // 0..1
    const int wy = warp >> 1;         // 0..3
    const int lx = (wx * 8 + tx) * OPT;     // 0..60
    const int ly = (wy * 4 + sy) * 2;       // 0,2,..,30 (first output row)

    unsigned long long acc[2][OPT];   // {Sum E*h, Sum F*g}
    float den[2][OPT];
    #pragma unroll
    for (int r = 0; r < 2; r++)
        #pragma unroll
        for (int o = 0; o < OPT; o++) { acc[r][o] = 0ull; den[r][o] = 0.f; }

    // Loop over the 8 input rows of this thread's footprint; load once,
    // feed both output rows.
    #pragma unroll
    for (int r = 0; r < KH + 1; r++) {
        const float* gr = &sG[(ly + r) * PITCH + lx];
        const float* hr = &sH[(ly + r) * PITCH + lx];
        float g[WINW];
        unsigned long long w[WINW];   // {h, g}
        #pragma unroll
        for (int j = 0; j < WINW; j++) {
            float hv = hr[j];                     // LDS.32, conflict-free
            g[j] = gr[j];                         // LDS.32, conflict-free
            asm("mov.b64 %0, {%1, %2};" : "=l"(w[j]) : "f"(hv), "f"(g[j]));
        }

        // out-row 0 uses tap row r (valid for r = 0..6)
        if (r <= KH - 1) {
            const unsigned long long* efr =
                reinterpret_cast<const unsigned long long*>(&sEF[r * KW]);
            #pragma unroll
            for (int kx = 0; kx < KW; kx++) {
                const unsigned long long ef = efr[kx];  // LDS.64 broadcast {E,F}
                const float E = sE[r * KW + kx];        // LDS.32 broadcast
                #pragma unroll
                for (int o = 0; o < OPT; o++) {
                    vfma(acc[0][o], ef, w[kx + o]);
                    den[0][o] = fmaf(E, g[kx + o], den[0][o]);
                }
            }
        }
        // out-row 1 uses tap row r-1 (valid for r = 1..7)
        if (r >= 1) {
            const unsigned long long* efr =
                reinterpret_cast<const unsigned long long*>(&sEF[(r - 1) * KW]);
            #pragma unroll
            for (int kx = 0; kx < KW; kx++) {
                const unsigned long long ef = efr[kx];
                const float E = sE[(r - 1) * KW + kx];
                #pragma unroll
                for (int o = 0; o < OPT; o++) {
                    vfma(acc[1][o], ef, w[kx + o]);
                    den[1][o] = fmaf(E, g[kx + o], den[1][o]);
                }
            }
        }
    }

    const int ox = gx0 + lx;
    #pragma unroll
    for (int r = 0; r < 2; r++) {
        const int oy = gy0 + ly + r;
        if (oy < HO) {
            float* orow = out + ((long)bc * HO + oy) * WO;
            float v[OPT];
            #pragma unroll
            for (int o = 0; o < OPT; o++) {
                float pA, pB;
                asm("mov.b64 {%0, %1}, %2;" : "=f"(pA), "=f"(pB) : "l"(acc[r][o]));
                v[o] = __fdividef(pA + pB, den[r][o]);
            }
            if (ox + 3 < WO) {
                // row base 8B-aligned (WO even), not 16B for odd oy: 2x STG.64
                *reinterpret_cast<float2*>(orow + ox)     = make_float2(v[0], v[1]);
                *reinterpret_cast<float2*>(orow + ox + 2) = make_float2(v[2], v[3]);
            } else {
                #pragma unroll
                for (int o = 0; o < OPT; o++)
                    if (ox + o < WO) orow[ox + o] = v[o];
            }
        }
    }
}

extern "C" void kernel_launch(void* const* d_in, const int* in_sizes, int n_in,
                              void* d_out, int out_size) {
    const float* x     = (const float*)d_in[0];   // (8,1,192,192)
    const float* filt  = (const float*)d_in[1];   // (8,1,7,7)
    const float* alpha = (const float*)d_in[2];   // (8,1)
    float* out = (float*)d_out;                   // (8,8,186,186)

    dim3 block(256);
    dim3 grid((WO + TILE_X - 1) / TILE_X,   // 3
              (HO + TILE_Y - 1) / TILE_Y,   // 6
              BATCH * CO);                  // 64
    smorph_kernel<<<grid, block>>>(x, filt, alpha, out);
}